// round 10
// baseline (speedup 1.0000x reference)
#include <cuda_runtime.h>
#include <cuda_fp16.h>
#include <cstdint>
#include <math.h>

#define BATCH 8192
#define HID   1024
#define M1    1048576

// ---------------- device scratch (no allocations allowed) ----------------
__device__ __half g_w16[10 * M1];
__device__ __half g_x16[BATCH * HID];
__device__ __half g_h16[BATCH * HID];
__device__ __half g_rh16[BATCH * HID];
__device__ __half g_z16[BATCH * HID];
__device__ __half g_c16[BATCH * HID];
__device__ __half g_hat16[BATCH * HID];

#define OFF_WXR  0
#define OFF_WHR  (1 * M1)
#define OFF_WXZ  (2 * M1)
#define OFF_WHZ  (3 * M1)
#define OFF_WXH  (4 * M1)
#define OFF_WHH  (5 * M1)
#define OFF_WC   (6 * M1)
#define OFF_WHAT (8 * M1)

// ---------------- helpers ----------------
__device__ __forceinline__ uint32_t smem_u32(const void* p) {
    uint32_t a;
    asm("{ .reg .u64 t; cvta.to.shared.u64 t, %1; cvt.u32.u64 %0, t; }" : "=r"(a) : "l"(p));
    return a;
}
__device__ __forceinline__ void cp16(uint32_t s, const void* g) {
    asm volatile("cp.async.cg.shared.global [%0], [%1], 16;" :: "r"(s), "l"(g));
}
__device__ __forceinline__ void ldsm4(uint32_t (&r)[4], uint32_t addr) {
    asm volatile("ldmatrix.sync.aligned.m8n8.x4.shared.b16 {%0,%1,%2,%3}, [%4];"
        : "=r"(r[0]), "=r"(r[1]), "=r"(r[2]), "=r"(r[3]) : "r"(addr));
}
__device__ __forceinline__ void mma_f16(float (&d)[4], const uint32_t (&a)[4],
                                        uint32_t b0, uint32_t b1) {
    asm volatile("mma.sync.aligned.m16n8k16.row.col.f32.f16.f16.f32 "
        "{%0,%1,%2,%3}, {%4,%5,%6,%7}, {%8,%9}, {%0,%1,%2,%3};"
        : "+f"(d[0]), "+f"(d[1]), "+f"(d[2]), "+f"(d[3])
        : "r"(a[0]), "r"(a[1]), "r"(a[2]), "r"(a[3]), "r"(b0), "r"(b1));
}
__device__ __forceinline__ float fast_tanh(float x) {
    float r;
    asm("tanh.approx.f32 %0, %1;" : "=f"(r) : "f"(x));
    return r;
}
__device__ __forceinline__ float fast_sigmoid(float x) {
    return fmaf(fast_tanh(0.5f * x), 0.5f, 0.5f);
}

// ---------------- GEMM config ----------------
// BM=64, BN=128, 8 warps (2M x 4N), warp tile 32x32 (MT=2).
// 3 stages x 24KB = 72KB smem -> 3 CTAs/SM (24 warps).
#define THREADS 256
#define MT 2
#define AROWS 64
#define ABYTES (AROWS * 128)
#define STAGE (ABYTES + 16384)
#define SMEM_TOTAL (3 * STAGE)

__device__ __forceinline__ void load_chunk(uint32_t sA, uint32_t sB,
    const __half* __restrict__ a, const __half* __restrict__ b,
    int ldb, int m0, int bn, int k0, int tid)
{
#pragma unroll
    for (int it = 0; it < 2; it++) {
        int s = tid + it * 256;
        int r = s >> 3, cc = s & 7;
        uint32_t off = r * 128 + ((cc * 16) ^ ((r & 7) << 4));
        cp16(sA + off, a + (size_t)(m0 + r) * 1024 + k0 + cc * 8);
    }
#pragma unroll
    for (int it = 0; it < 4; it++) {
        int s = tid + it * 256;
        int r = s >> 3, cc = s & 7;
        uint32_t off = r * 128 + ((cc * 16) ^ ((r & 7) << 4));
        cp16(sB + off, b + (size_t)(bn + r) * (size_t)ldb + k0 + cc * 8);
    }
    asm volatile("cp.async.commit_group;" ::: "memory");
}

// FINAL=0: o=0..3 (r,z,c,hat), grid (32, 128): o=bx>>3, bn=(bx&7)*128
// FINAL=1: pairs {rh@Whh^T, x@Wxh^T} accumulated -> fused output, grid (8, 128)
template <int FINAL>
__global__ __launch_bounds__(THREADS, 3)
void gemm_tc(const float* __restrict__ br, const float* __restrict__ bz,
             const float* __restrict__ bh, const float* __restrict__ bc,
             const float* __restrict__ bhat, const float* __restrict__ hprev,
             float* __restrict__ out)
{
    extern __shared__ char smem[];
    const uint32_t sb = smem_u32(smem);
    const int tid = threadIdx.x;
    const int lane = tid & 31;
    const int wid = tid >> 5;
    const int wm = wid >> 2;
    const int wn = wid & 3;
    const int m0 = blockIdx.y * 64;

    int o, bn;
    if (FINAL) { o = 4; bn = blockIdx.x * 128; }
    else       { o = blockIdx.x >> 3; bn = (blockIdx.x & 7) * 128; }

    const __half *aSrc[2] = {g_x16, g_h16};
    const __half *bSrc[2] = {0, 0};
    int ldbv = 1024;
    const float* bias = 0;
    switch (o) {
        case 0: bSrc[0] = g_w16 + OFF_WXR; bSrc[1] = g_w16 + OFF_WHR; bias = br; break;
        case 1: bSrc[0] = g_w16 + OFF_WXZ; bSrc[1] = g_w16 + OFF_WHZ; bias = bz; break;
        case 2: bSrc[0] = g_w16 + OFF_WC;  bSrc[1] = g_w16 + OFF_WC + 1024;
                ldbv = 2048; bias = bc; break;
        case 3: bSrc[0] = g_w16 + OFF_WHAT; bSrc[1] = g_w16 + OFF_WHAT + 1024;
                ldbv = 2048; bias = bhat; break;
        default: aSrc[0] = g_rh16; aSrc[1] = g_x16;
                 bSrc[0] = g_w16 + OFF_WHH; bSrc[1] = g_w16 + OFF_WXH;
                 bias = bh; break;
    }

    uint32_t aC[MT];
#pragma unroll
    for (int mt = 0; mt < MT; mt++) {
        int r = wm * 32 + mt * 16 + (lane & 15);
        aC[mt] = (uint32_t)(r * 128) | (uint32_t)((r & 7) << 4);
    }
    const uint32_t acx = (uint32_t)((lane >> 4) << 4);
    uint32_t bC[2];
#pragma unroll
    for (int nt = 0; nt < 2; nt++) {
        int r = wn * 32 + nt * 16 + (lane & 7) + ((lane >> 4) << 3);
        bC[nt] = (uint32_t)(r * 128) | (uint32_t)((r & 7) << 4);
    }
    const uint32_t bcx = (uint32_t)(((lane >> 3) & 1) << 4);

    float acc[MT][4][4];
#pragma unroll
    for (int i = 0; i < MT; i++)
#pragma unroll
        for (int j = 0; j < 4; j++)
#pragma unroll
            for (int k = 0; k < 4; k++) acc[i][j][k] = 0.0f;

    const int total = 32;   // 2 pairs x 16 K-chunks of 64

    load_chunk(sb + 0 * STAGE, sb + 0 * STAGE + ABYTES,
               aSrc[0], bSrc[0], ldbv, m0, bn, 0, tid);
    load_chunk(sb + 1 * STAGE, sb + 1 * STAGE + ABYTES,
               aSrc[0], bSrc[0], ldbv, m0, bn, 64, tid);

    for (int ch = 0; ch < total; ch++) {
        if (ch == total - 1) asm volatile("cp.async.wait_group 0;" ::: "memory");
        else                 asm volatile("cp.async.wait_group 1;" ::: "memory");
        __syncthreads();

        int nc = ch + 2;
        if (nc < total) {
            int p = nc >> 4;
            int st = nc % 3;
            load_chunk(sb + st * STAGE, sb + st * STAGE + ABYTES,
                       aSrc[p], bSrc[p], ldbv, m0, bn, (nc & 15) * 64, tid);
        }

        const uint32_t sA = sb + (ch % 3) * STAGE;
        const uint32_t sB = sA + ABYTES;

        uint32_t Af[2][MT][4], Bf[2][2][4];
#pragma unroll
        for (int mt = 0; mt < MT; mt++) ldsm4(Af[0][mt], sA + (aC[mt] ^ acx));
#pragma unroll
        for (int nt = 0; nt < 2; nt++) ldsm4(Bf[0][nt], sB + (bC[nt] ^ bcx));
#pragma unroll
        for (int ks = 0; ks < 4; ks++) {
            const int cur = ks & 1, nxt = cur ^ 1;
            if (ks < 3) {
                const uint32_t qa = ((uint32_t)(ks + 1) << 5) | acx;
                const uint32_t qb = ((uint32_t)(ks + 1) << 5) | bcx;
#pragma unroll
                for (int mt = 0; mt < MT; mt++) ldsm4(Af[nxt][mt], sA + (aC[mt] ^ qa));
#pragma unroll
                for (int nt = 0; nt < 2; nt++) ldsm4(Bf[nxt][nt], sB + (bC[nt] ^ qb));
            }
#pragma unroll
            for (int mt = 0; mt < MT; mt++)
#pragma unroll
                for (int j = 0; j < 4; j++)
                    mma_f16(acc[mt][j], Af[cur][mt],
                            Bf[cur][j >> 1][(j & 1) * 2], Bf[cur][j >> 1][(j & 1) * 2 + 1]);
        }
    }

    // ---------------- fused epilogue ----------------
#pragma unroll
    for (int mt = 0; mt < MT; mt++) {
#pragma unroll
        for (int j = 0; j < 4; j++) {
            const int c0 = bn + wn * 32 + j * 8 + (lane & 3) * 2;
#pragma unroll
            for (int half = 0; half < 2; half++) {
                const int row = m0 + wm * 32 + mt * 16 + (lane >> 2) + half * 8;
                const size_t idx = (size_t)row * HID + c0;
                float v0 = acc[mt][j][half * 2 + 0];
                float v1 = acc[mt][j][half * 2 + 1];
                if (FINAL) {
                    float t0 = fast_tanh(v0 + bias[c0]);
                    float t1 = fast_tanh(v1 + bias[c0 + 1]);
                    float2 zz = __half22float2(*(const __half2*)(g_z16 + idx));
                    float2 hh = __half22float2(*(const __half2*)(g_hat16 + idx));
                    out[idx]     = (1.0f - zz.x) * t0 + zz.x * hprev[idx]     + hh.x;
                    out[idx + 1] = (1.0f - zz.y) * t1 + zz.y * hprev[idx + 1] + hh.y;
                } else if (o == 0) {
                    float s0 = fast_sigmoid(v0 + bias[c0]);
                    float s1 = fast_sigmoid(v1 + bias[c0 + 1]);
                    float rh0 = s0 * hprev[idx], rh1 = s1 * hprev[idx + 1];
                    *(__half2*)(g_rh16 + idx) = __floats2half2_rn(rh0, rh1);
                } else if (o == 1) {
                    *(__half2*)(g_z16 + idx) =
                        __floats2half2_rn(fast_sigmoid(v0 + bias[c0]), fast_sigmoid(v1 + bias[c0 + 1]));
                } else if (o == 2) {
                    *(__half2*)(g_c16 + idx) = __floats2half2_rn(v0 + bias[c0], v1 + bias[c0 + 1]);
                } else {
                    *(__half2*)(g_hat16 + idx) =
                        __floats2half2_rn(fmaxf(v0 + bias[c0], 0.0f), fmaxf(v1 + bias[c0 + 1], 0.0f));
                }
            }
        }
    }
}

// ---------------- batched fp32 -> fp16 convert (one launch) ----------------
struct ConvJob {
    const float4* src[10];
    __half2* dst[10];
    int end4[10];
};

#define CONV_TOTAL4 6815744

__global__ __launch_bounds__(256)
void convall(ConvJob j)
{
    const int gid = blockIdx.x * 256 + threadIdx.x;
#pragma unroll
    for (int rep = 0; rep < 2; rep++) {
        int i = gid + rep * (CONV_TOTAL4 / 2);
        int s = 0;
#pragma unroll
        for (int t = 0; t < 9; t++) s += (i >= j.end4[t]) ? 1 : 0;
        int base = (s == 0) ? 0 : j.end4[s - 1];
        int k = i - base;
        float4 f = j.src[s][k];
        j.dst[s][2 * k]     = __floats2half2_rn(f.x, f.y);
        j.dst[s][2 * k + 1] = __floats2half2_rn(f.z, f.w);
    }
}

// ---------------- row softmax: g_hat16 *= softmax(g_c16) ----------------
__global__ __launch_bounds__(256)
void softmax_kernel()
{
    const int row = blockIdx.x;
    const int tid = threadIdx.x;
    const size_t base2 = (size_t)row * 512;
    const __half2* c2 = (const __half2*)g_c16;
    __half2* t2 = (__half2*)g_hat16;
    __shared__ float sh[8];

    float2 v[2];
    float mx = -1e30f;
#pragma unroll
    for (int i = 0; i < 2; i++) {
        v[i] = __half22float2(c2[base2 + tid + i * 256]);
        mx = fmaxf(mx, fmaxf(v[i].x, v[i].y));
    }
#pragma unroll
    for (int off = 16; off > 0; off >>= 1) mx = fmaxf(mx, __shfl_xor_sync(0xffffffffu, mx, off));
    if ((tid & 31) == 0) sh[tid >> 5] = mx;
    __syncthreads();
    mx = sh[0];
#pragma unroll
    for (int i = 1; i < 8; i++) mx = fmaxf(mx, sh[i]);
    __syncthreads();

    float s = 0.0f;
#pragma unroll
    for (int i = 0; i < 2; i++) {
        v[i].x = __expf(v[i].x - mx);
        v[i].y = __expf(v[i].y - mx);
        s += v[i].x + v[i].y;
    }
#pragma unroll
    for (int off = 16; off > 0; off >>= 1) s += __shfl_xor_sync(0xffffffffu, s, off);
    if ((tid & 31) == 0) sh[tid >> 5] = s;
    __syncthreads();
    s = 0.0f;
#pragma unroll
    for (int i = 0; i < 8; i++) s += sh[i];
    const float inv = 1.0f / s;

#pragma unroll
    for (int i = 0; i < 2; i++) {
        size_t idx = base2 + tid + i * 256;
        float2 hh = __half22float2(t2[idx]);
        t2[idx] = __floats2half2_rn(hh.x * v[i].x * inv, hh.y * v[i].y * inv);
    }
}

extern "C" void kernel_launch(void* const* d_in, const int* in_sizes, int n_in,
                              void* d_out, int out_size)
{
    (void)in_sizes; (void)n_in; (void)out_size;
    const float* x    = (const float*)d_in[0];
    const float* h    = (const float*)d_in[1];
    const float* Wxr  = (const float*)d_in[2];
    const float* Whr  = (const float*)d_in[3];
    const float* br   = (const float*)d_in[4];
    const float* Wxz  = (const float*)d_in[5];
    const float* Whz  = (const float*)d_in[6];
    const float* bz   = (const float*)d_in[7];
    const float* Wxh  = (const float*)d_in[8];
    const float* Whh  = (const float*)d_in[9];
    const float* bh   = (const float*)d_in[10];
    const float* Wc   = (const float*)d_in[11];
    const float* bc   = (const float*)d_in[12];
    const float* What = (const float*)d_in[13];
    const float* bhat = (const float*)d_in[14];
    float* out = (float*)d_out;

    __half *w16, *x16, *h16;
    cudaGetSymbolAddress((void**)&w16, g_w16);
    cudaGetSymbolAddress((void**)&x16, g_x16);
    cudaGetSymbolAddress((void**)&h16, g_h16);

    cudaFuncSetAttribute(gemm_tc<0>, cudaFuncAttributeMaxDynamicSharedMemorySize, SMEM_TOTAL);
    cudaFuncSetAttribute(gemm_tc<1>, cudaFuncAttributeMaxDynamicSharedMemorySize, SMEM_TOTAL);

    ConvJob j;
    const float* srcs[10] = {x, h, Wxr, Whr, Wxz, Whz, Wxh, Whh, Wc, What};
    __half* dsts[10] = {x16, h16, w16 + OFF_WXR, w16 + OFF_WHR, w16 + OFF_WXZ,
                        w16 + OFF_WHZ, w16 + OFF_WXH, w16 + OFF_WHH,
                        w16 + OFF_WC, w16 + OFF_WHAT};
    const int cnt4[10] = {2097152, 2097152, 262144, 262144, 262144, 262144,
                          262144, 262144, 524288, 524288};
    int acc4 = 0;
    for (int i = 0; i < 10; i++) {
        j.src[i] = (const float4*)srcs[i];
        j.dst[i] = (__half2*)dsts[i];
        acc4 += cnt4[i];
        j.end4[i] = acc4;
    }

    convall<<<CONV_TOTAL4 / 2 / 256, 256>>>(j);

    // fused multi-output GEMM: r (->rh fp16), z16, c16, hat16
    gemm_tc<0><<<dim3(32, 128), THREADS, SMEM_TOTAL>>>(br, bz, bh, bc, bhat, h, nullptr);

    // g_hat16 *= softmax(g_c16)
    softmax_kernel<<<BATCH, 256>>>();

    // final: acc = rh@Whh^T + x@Wxh^T ; out = (1-z)*tanh(acc+bh) + z*h + hat
    gemm_tc<1><<<dim3(8, 128), THREADS, SMEM_TOTAL>>>(br, bz, bh, bc, bhat, h, out);
}

// round 11
// speedup vs baseline: 1.0762x; 1.0762x over previous
#include <cuda_runtime.h>
#include <cuda_fp16.h>
#include <cstdint>
#include <math.h>

#define BATCH 8192
#define HID   1024
#define M1    1048576

// ---------------- device scratch (no allocations allowed) ----------------
__device__ __half g_w16[10 * M1];
__device__ __half g_x16[BATCH * HID];
__device__ __half g_h16[BATCH * HID];
__device__ __half g_rh16[BATCH * HID];
__device__ __half g_z16[BATCH * HID];
__device__ __half g_ec16[BATCH * HID];   // exp(c_pre + bc)
__device__ __half g_hat16[BATCH * HID];  // relu(hat_pre + bhat), unscaled
__device__ float  g_inv[BATCH];          // 1 / rowsum(exp(c))

#define OFF_WXR  0
#define OFF_WHR  (1 * M1)
#define OFF_WXZ  (2 * M1)
#define OFF_WHZ  (3 * M1)
#define OFF_WXH  (4 * M1)
#define OFF_WHH  (5 * M1)
#define OFF_WC   (6 * M1)
#define OFF_WHAT (8 * M1)

// ---------------- helpers ----------------
__device__ __forceinline__ uint32_t smem_u32(const void* p) {
    uint32_t a;
    asm("{ .reg .u64 t; cvta.to.shared.u64 t, %1; cvt.u32.u64 %0, t; }" : "=r"(a) : "l"(p));
    return a;
}
__device__ __forceinline__ void cp16(uint32_t s, const void* g) {
    asm volatile("cp.async.cg.shared.global [%0], [%1], 16;" :: "r"(s), "l"(g));
}
__device__ __forceinline__ void ldsm4(uint32_t (&r)[4], uint32_t addr) {
    asm volatile("ldmatrix.sync.aligned.m8n8.x4.shared.b16 {%0,%1,%2,%3}, [%4];"
        : "=r"(r[0]), "=r"(r[1]), "=r"(r[2]), "=r"(r[3]) : "r"(addr));
}
__device__ __forceinline__ void mma_f16(float (&d)[4], const uint32_t (&a)[4],
                                        uint32_t b0, uint32_t b1) {
    asm volatile("mma.sync.aligned.m16n8k16.row.col.f32.f16.f16.f32 "
        "{%0,%1,%2,%3}, {%4,%5,%6,%7}, {%8,%9}, {%0,%1,%2,%3};"
        : "+f"(d[0]), "+f"(d[1]), "+f"(d[2]), "+f"(d[3])
        : "r"(a[0]), "r"(a[1]), "r"(a[2]), "r"(a[3]), "r"(b0), "r"(b1));
}
__device__ __forceinline__ float fast_tanh(float x) {
    float r;
    asm("tanh.approx.f32 %0, %1;" : "=f"(r) : "f"(x));
    return r;
}
__device__ __forceinline__ float fast_sigmoid(float x) {
    return fmaf(fast_tanh(0.5f * x), 0.5f, 0.5f);
}

// ---------------- GEMM config (R8 champion: BM=128, 2 CTA/SM, MT=4) ----------------
#define THREADS 256
#define STAGE_BYTES 16384
#define SMEM_TOTAL (3 * 2 * STAGE_BYTES)

__device__ __forceinline__ void load_chunk(uint32_t sA, uint32_t sB,
    const __half* __restrict__ a, const __half* __restrict__ b,
    int ldb, int m0, int bn, int k0, int tid)
{
#pragma unroll
    for (int it = 0; it < 4; it++) {
        int s = tid + it * 256;
        int r = s >> 3, cc = s & 7;
        uint32_t off = r * 128 + ((cc * 16) ^ ((r & 7) << 4));
        cp16(sA + off, a + (size_t)(m0 + r) * 1024 + k0 + cc * 8);
    }
#pragma unroll
    for (int it = 0; it < 4; it++) {
        int s = tid + it * 256;
        int r = s >> 3, cc = s & 7;
        uint32_t off = r * 128 + ((cc * 16) ^ ((r & 7) << 4));
        cp16(sB + off, b + (size_t)(bn + r) * (size_t)ldb + k0 + cc * 8);
    }
    asm volatile("cp.async.commit_group;" ::: "memory");
}

// FINAL=0: o=0..3 (r,z,expc,hat), grid (32, 64): o=bx>>3, bn=(bx&7)*128 — all 32-chunk
// FINAL=1: pairs {rh@Whh^T, x@Wxh^T} accumulated -> fused output, grid (8, 64)
template <int FINAL>
__global__ __launch_bounds__(THREADS, 2)
void gemm_tc(const float* __restrict__ br, const float* __restrict__ bz,
             const float* __restrict__ bh, const float* __restrict__ bc,
             const float* __restrict__ bhat, const float* __restrict__ hprev,
             float* __restrict__ out)
{
    extern __shared__ char smem[];
    const uint32_t sb = smem_u32(smem);
    const int tid = threadIdx.x;
    const int lane = tid & 31;
    const int wid = tid >> 5;
    const int wm = wid >> 2;
    const int wn = wid & 3;
    const int m0 = blockIdx.y * 128;

    int o, bn;
    if (FINAL) { o = 4; bn = blockIdx.x * 128; }
    else       { o = blockIdx.x >> 3; bn = (blockIdx.x & 7) * 128; }

    const __half *aSrc[2] = {g_x16, g_h16};
    const __half *bSrc[2] = {0, 0};
    int ldbv = 1024;
    const float* bias = 0;
    switch (o) {
        case 0: bSrc[0] = g_w16 + OFF_WXR; bSrc[1] = g_w16 + OFF_WHR; bias = br; break;
        case 1: bSrc[0] = g_w16 + OFF_WXZ; bSrc[1] = g_w16 + OFF_WHZ; bias = bz; break;
        case 2: bSrc[0] = g_w16 + OFF_WC;  bSrc[1] = g_w16 + OFF_WC + 1024;
                ldbv = 2048; bias = bc; break;
        case 3: bSrc[0] = g_w16 + OFF_WHAT; bSrc[1] = g_w16 + OFF_WHAT + 1024;
                ldbv = 2048; bias = bhat; break;
        default: aSrc[0] = g_rh16; aSrc[1] = g_x16;
                 bSrc[0] = g_w16 + OFF_WHH; bSrc[1] = g_w16 + OFF_WXH;
                 bias = bh; break;
    }

    uint32_t aC[4];
#pragma unroll
    for (int mt = 0; mt < 4; mt++) {
        int r = wm * 64 + mt * 16 + (lane & 15);
        aC[mt] = (uint32_t)(r * 128) | (uint32_t)((r & 7) << 4);
    }
    const uint32_t acx = (uint32_t)((lane >> 4) << 4);
    uint32_t bC[2];
#pragma unroll
    for (int nt = 0; nt < 2; nt++) {
        int r = wn * 32 + nt * 16 + (lane & 7) + ((lane >> 4) << 3);
        bC[nt] = (uint32_t)(r * 128) | (uint32_t)((r & 7) << 4);
    }
    const uint32_t bcx = (uint32_t)(((lane >> 3) & 1) << 4);

    float acc[4][4][4];
#pragma unroll
    for (int i = 0; i < 4; i++)
#pragma unroll
        for (int j = 0; j < 4; j++)
#pragma unroll
            for (int k = 0; k < 4; k++) acc[i][j][k] = 0.0f;

    const int total = 32;   // 2 pairs x 16 K-chunks of 64

    load_chunk(sb + 0 * STAGE_BYTES * 2, sb + 0 * STAGE_BYTES * 2 + STAGE_BYTES,
               aSrc[0], bSrc[0], ldbv, m0, bn, 0, tid);
    load_chunk(sb + 1 * STAGE_BYTES * 2, sb + 1 * STAGE_BYTES * 2 + STAGE_BYTES,
               aSrc[0], bSrc[0], ldbv, m0, bn, 64, tid);

    for (int ch = 0; ch < total; ch++) {
        if (ch == total - 1) asm volatile("cp.async.wait_group 0;" ::: "memory");
        else                 asm volatile("cp.async.wait_group 1;" ::: "memory");
        __syncthreads();

        int nc = ch + 2;
        if (nc < total) {
            int p = nc >> 4;
            int st = nc % 3;
            load_chunk(sb + st * STAGE_BYTES * 2, sb + st * STAGE_BYTES * 2 + STAGE_BYTES,
                       aSrc[p], bSrc[p], ldbv, m0, bn, (nc & 15) * 64, tid);
        }

        const uint32_t sA = sb + (ch % 3) * STAGE_BYTES * 2;
        const uint32_t sB = sA + STAGE_BYTES;

        uint32_t Af[2][4][4], Bf[2][2][4];
#pragma unroll
        for (int mt = 0; mt < 4; mt++) ldsm4(Af[0][mt], sA + (aC[mt] ^ acx));
#pragma unroll
        for (int nt = 0; nt < 2; nt++) ldsm4(Bf[0][nt], sB + (bC[nt] ^ bcx));
#pragma unroll
        for (int ks = 0; ks < 4; ks++) {
            const int cur = ks & 1, nxt = cur ^ 1;
            if (ks < 3) {
                const uint32_t qa = ((uint32_t)(ks + 1) << 5) | acx;
                const uint32_t qb = ((uint32_t)(ks + 1) << 5) | bcx;
#pragma unroll
                for (int mt = 0; mt < 4; mt++) ldsm4(Af[nxt][mt], sA + (aC[mt] ^ qa));
#pragma unroll
                for (int nt = 0; nt < 2; nt++) ldsm4(Bf[nxt][nt], sB + (bC[nt] ^ qb));
            }
#pragma unroll
            for (int mt = 0; mt < 4; mt++)
#pragma unroll
                for (int j = 0; j < 4; j++)
                    mma_f16(acc[mt][j], Af[cur][mt],
                            Bf[cur][j >> 1][(j & 1) * 2], Bf[cur][j >> 1][(j & 1) * 2 + 1]);
        }
    }

    // ---------------- fused epilogue ----------------
#pragma unroll
    for (int mt = 0; mt < 4; mt++) {
#pragma unroll
        for (int j = 0; j < 4; j++) {
            const int c0 = bn + wn * 32 + j * 8 + (lane & 3) * 2;
#pragma unroll
            for (int half = 0; half < 2; half++) {
                const int row = m0 + wm * 64 + mt * 16 + (lane >> 2) + half * 8;
                const size_t idx = (size_t)row * HID + c0;
                float v0 = acc[mt][j][half * 2 + 0];
                float v1 = acc[mt][j][half * 2 + 1];
                if (FINAL) {
                    float t0 = fast_tanh(v0 + bias[c0]);
                    float t1 = fast_tanh(v1 + bias[c0 + 1]);
                    float2 zz = __half22float2(*(const __half2*)(g_z16 + idx));
                    float2 hh = __half22float2(*(const __half2*)(g_hat16 + idx));
                    float2 ec = __half22float2(*(const __half2*)(g_ec16 + idx));
                    float inv = g_inv[row];
                    out[idx]     = (1.0f - zz.x) * t0 + zz.x * hprev[idx]     + hh.x * ec.x * inv;
                    out[idx + 1] = (1.0f - zz.y) * t1 + zz.y * hprev[idx + 1] + hh.y * ec.y * inv;
                } else if (o == 0) {
                    float s0 = fast_sigmoid(v0 + bias[c0]);
                    float s1 = fast_sigmoid(v1 + bias[c0 + 1]);
                    float2 hh = __half22float2(*(const __half2*)(g_h16 + idx));
                    *(__half2*)(g_rh16 + idx) = __floats2half2_rn(s0 * hh.x, s1 * hh.y);
                } else if (o == 1) {
                    *(__half2*)(g_z16 + idx) =
                        __floats2half2_rn(fast_sigmoid(v0 + bias[c0]), fast_sigmoid(v1 + bias[c0 + 1]));
                } else if (o == 2) {
                    *(__half2*)(g_ec16 + idx) =
                        __floats2half2_rn(__expf(v0 + bias[c0]), __expf(v1 + bias[c0 + 1]));
                } else {
                    *(__half2*)(g_hat16 + idx) =
                        __floats2half2_rn(fmaxf(v0 + bias[c0], 0.0f), fmaxf(v1 + bias[c0 + 1], 0.0f));
                }
            }
        }
    }
}

// ---------------- batched fp32 -> fp16 convert (one launch) ----------------
struct ConvJob {
    const float4* src[10];
    __half2* dst[10];
    int end4[10];
};

#define CONV_TOTAL4 6815744

__global__ __launch_bounds__(256)
void convall(ConvJob j)
{
    const int gid = blockIdx.x * 256 + threadIdx.x;
#pragma unroll
    for (int rep = 0; rep < 2; rep++) {
        int i = gid + rep * (CONV_TOTAL4 / 2);
        int s = 0;
#pragma unroll
        for (int t = 0; t < 9; t++) s += (i >= j.end4[t]) ? 1 : 0;
        int base = (s == 0) ? 0 : j.end4[s - 1];
        int k = i - base;
        float4 f = j.src[s][k];
        j.dst[s][2 * k]     = __floats2half2_rn(f.x, f.y);
        j.dst[s][2 * k + 1] = __floats2half2_rn(f.z, f.w);
    }
}

// ---------------- row sum of exp(c): g_inv[row] = 1/sum ----------------
__global__ __launch_bounds__(256)
void rowsum_kernel()
{
    const int row = blockIdx.x;
    const int tid = threadIdx.x;
    const size_t base2 = (size_t)row * 512;
    const __half2* c2 = (const __half2*)g_ec16;
    __shared__ float sh[8];

    float s = 0.0f;
#pragma unroll
    for (int i = 0; i < 2; i++) {
        float2 v = __half22float2(c2[base2 + tid + i * 256]);
        s += v.x + v.y;
    }
#pragma unroll
    for (int off = 16; off > 0; off >>= 1) s += __shfl_xor_sync(0xffffffffu, s, off);
    if ((tid & 31) == 0) sh[tid >> 5] = s;
    __syncthreads();
    if (tid == 0) {
        float t = 0.0f;
#pragma unroll
        for (int i = 0; i < 8; i++) t += sh[i];
        g_inv[row] = 1.0f / t;
    }
}

extern "C" void kernel_launch(void* const* d_in, const int* in_sizes, int n_in,
                              void* d_out, int out_size)
{
    (void)in_sizes; (void)n_in; (void)out_size;
    const float* x    = (const float*)d_in[0];
    const float* h    = (const float*)d_in[1];
    const float* Wxr  = (const float*)d_in[2];
    const float* Whr  = (const float*)d_in[3];
    const float* br   = (const float*)d_in[4];
    const float* Wxz  = (const float*)d_in[5];
    const float* Whz  = (const float*)d_in[6];
    const float* bz   = (const float*)d_in[7];
    const float* Wxh  = (const float*)d_in[8];
    const float* Whh  = (const float*)d_in[9];
    const float* bh   = (const float*)d_in[10];
    const float* Wc   = (const float*)d_in[11];
    const float* bc   = (const float*)d_in[12];
    const float* What = (const float*)d_in[13];
    const float* bhat = (const float*)d_in[14];
    float* out = (float*)d_out;

    __half *w16, *x16, *h16;
    cudaGetSymbolAddress((void**)&w16, g_w16);
    cudaGetSymbolAddress((void**)&x16, g_x16);
    cudaGetSymbolAddress((void**)&h16, g_h16);

    cudaFuncSetAttribute(gemm_tc<0>, cudaFuncAttributeMaxDynamicSharedMemorySize, SMEM_TOTAL);
    cudaFuncSetAttribute(gemm_tc<1>, cudaFuncAttributeMaxDynamicSharedMemorySize, SMEM_TOTAL);

    ConvJob j;
    const float* srcs[10] = {x, h, Wxr, Whr, Wxz, Whz, Wxh, Whh, Wc, What};
    __half* dsts[10] = {x16, h16, w16 + OFF_WXR, w16 + OFF_WHR, w16 + OFF_WXZ,
                        w16 + OFF_WHZ, w16 + OFF_WXH, w16 + OFF_WHH,
                        w16 + OFF_WC, w16 + OFF_WHAT};
    const int cnt4[10] = {2097152, 2097152, 262144, 262144, 262144, 262144,
                          262144, 262144, 524288, 524288};
    int acc4 = 0;
    for (int i = 0; i < 10; i++) {
        j.src[i] = (const float4*)srcs[i];
        j.dst[i] = (__half2*)dsts[i];
        acc4 += cnt4[i];
        j.end4[i] = acc4;
    }

    convall<<<CONV_TOTAL4 / 2 / 256, 256>>>(j);

    // fused multi-output GEMM: r (->rh fp16), z16, exp(c)16, hat16
    gemm_tc<0><<<dim3(32, 64), THREADS, SMEM_TOTAL>>>(br, bz, bh, bc, bhat, h, nullptr);

    // g_inv[row] = 1 / rowsum(exp(c))
    rowsum_kernel<<<BATCH, 256>>>();

    // final: acc = rh@Whh^T + x@Wxh^T ; out = (1-z)*tanh(acc+bh) + z*h + hat*ec*inv
    gemm_tc<1><<<dim3(8, 64), THREADS, SMEM_TOTAL>>>(br, bz, bh, bc, bhat, h, out);
}

// round 13
// speedup vs baseline: 1.0839x; 1.0072x over previous
#include <cuda_runtime.h>
#include <cuda_fp16.h>
#include <cstdint>
#include <math.h>

#define BATCH 8192
#define HID   1024
#define M1    1048576

// ---------------- device scratch (no allocations allowed) ----------------
__device__ __half g_w16[10 * M1];
__device__ __half g_x16[BATCH * HID];
__device__ __half g_h16[BATCH * HID];
__device__ __half g_rh16[BATCH * HID];
__device__ __half g_z16[BATCH * HID];
__device__ __half g_ec16[BATCH * HID];   // exp(c_pre + bc)
__device__ __half g_hat16[BATCH * HID];  // relu(hat_pre + bhat), unscaled
__device__ float  g_inv[BATCH];          // 1 / rowsum(exp(c))

#define OFF_WXR  0
#define OFF_WHR  (1 * M1)
#define OFF_WXZ  (2 * M1)
#define OFF_WHZ  (3 * M1)
#define OFF_WXH  (4 * M1)
#define OFF_WHH  (5 * M1)
#define OFF_WC   (6 * M1)
#define OFF_WHAT (8 * M1)

// ---------------- helpers ----------------
__device__ __forceinline__ uint32_t smem_u32(const void* p) {
    uint32_t a;
    asm("{ .reg .u64 t; cvta.to.shared.u64 t, %1; cvt.u32.u64 %0, t; }" : "=r"(a) : "l"(p));
    return a;
}
__device__ __forceinline__ void cp16(uint32_t s, const void* g) {
    asm volatile("cp.async.cg.shared.global [%0], [%1], 16;" :: "r"(s), "l"(g));
}
__device__ __forceinline__ void ldsm4(uint32_t (&r)[4], uint32_t addr) {
    asm volatile("ldmatrix.sync.aligned.m8n8.x4.shared.b16 {%0,%1,%2,%3}, [%4];"
        : "=r"(r[0]), "=r"(r[1]), "=r"(r[2]), "=r"(r[3]) : "r"(addr));
}
__device__ __forceinline__ void mma_f16(float (&d)[4], const uint32_t (&a)[4],
                                        uint32_t b0, uint32_t b1) {
    asm volatile("mma.sync.aligned.m16n8k16.row.col.f32.f16.f16.f32 "
        "{%0,%1,%2,%3}, {%4,%5,%6,%7}, {%8,%9}, {%0,%1,%2,%3};"
        : "+f"(d[0]), "+f"(d[1]), "+f"(d[2]), "+f"(d[3])
        : "r"(a[0]), "r"(a[1]), "r"(a[2]), "r"(a[3]), "r"(b0), "r"(b1));
}
__device__ __forceinline__ float fast_tanh(float x) {
    float r;
    asm("tanh.approx.f32 %0, %1;" : "=f"(r) : "f"(x));
    return r;
}
__device__ __forceinline__ float fast_sigmoid(float x) {
    return fmaf(fast_tanh(0.5f * x), 0.5f, 0.5f);
}

// ---------------- GEMM config (BM=128, 2 CTA/SM, MT=4) ----------------
#define THREADS 256
#define STAGE_BYTES 16384
#define SMEM_TOTAL (3 * 2 * STAGE_BYTES)

__device__ __forceinline__ void load_chunk(uint32_t sA, uint32_t sB,
    const __half* __restrict__ a, const __half* __restrict__ b,
    int ldb, int m0, int bn, int k0, int tid)
{
#pragma unroll
    for (int it = 0; it < 4; it++) {
        int s = tid + it * 256;
        int r = s >> 3, cc = s & 7;
        uint32_t off = r * 128 + ((cc * 16) ^ ((r & 7) << 4));
        cp16(sA + off, a + (size_t)(m0 + r) * 1024 + k0 + cc * 8);
    }
#pragma unroll
    for (int it = 0; it < 4; it++) {
        int s = tid + it * 256;
        int r = s >> 3, cc = s & 7;
        uint32_t off = r * 128 + ((cc * 16) ^ ((r & 7) << 4));
        cp16(sB + off, b + (size_t)(bn + r) * (size_t)ldb + k0 + cc * 8);
    }
    asm volatile("cp.async.commit_group;" ::: "memory");
}

// FINAL=0: o=0..3 (r,z,expc,hat), grid (32, 64): o=bx>>3, bn=(bx&7)*128 — all 32-chunk
// FINAL=1: pairs {rh@Whh^T, x@Wxh^T} accumulated -> fused output, grid (8, 64)
template <int FINAL>
__global__ __launch_bounds__(THREADS, 2)
void gemm_tc(const float* __restrict__ br, const float* __restrict__ bz,
             const float* __restrict__ bh, const float* __restrict__ bc,
             const float* __restrict__ bhat, float* __restrict__ out)
{
    extern __shared__ char smem[];
    const uint32_t sb = smem_u32(smem);
    const int tid = threadIdx.x;
    const int lane = tid & 31;
    const int wid = tid >> 5;
    const int wm = wid >> 2;
    const int wn = wid & 3;
    const int m0 = blockIdx.y * 128;

    int o, bn;
    if (FINAL) { o = 4; bn = blockIdx.x * 128; }
    else       { o = blockIdx.x >> 3; bn = (blockIdx.x & 7) * 128; }

    const __half *aSrc[2] = {g_x16, g_h16};
    const __half *bSrc[2] = {0, 0};
    int ldbv = 1024;
    const float* bias = 0;
    switch (o) {
        case 0: bSrc[0] = g_w16 + OFF_WXR; bSrc[1] = g_w16 + OFF_WHR; bias = br; break;
        case 1: bSrc[0] = g_w16 + OFF_WXZ; bSrc[1] = g_w16 + OFF_WHZ; bias = bz; break;
        case 2: bSrc[0] = g_w16 + OFF_WC;  bSrc[1] = g_w16 + OFF_WC + 1024;
                ldbv = 2048; bias = bc; break;
        case 3: bSrc[0] = g_w16 + OFF_WHAT; bSrc[1] = g_w16 + OFF_WHAT + 1024;
                ldbv = 2048; bias = bhat; break;
        default: aSrc[0] = g_rh16; aSrc[1] = g_x16;
                 bSrc[0] = g_w16 + OFF_WHH; bSrc[1] = g_w16 + OFF_WXH;
                 bias = bh; break;
    }

    uint32_t aC[4];
#pragma unroll
    for (int mt = 0; mt < 4; mt++) {
        int r = wm * 64 + mt * 16 + (lane & 15);
        aC[mt] = (uint32_t)(r * 128) | (uint32_t)((r & 7) << 4);
    }
    const uint32_t acx = (uint32_t)((lane >> 4) << 4);
    uint32_t bC[2];
#pragma unroll
    for (int nt = 0; nt < 2; nt++) {
        int r = wn * 32 + nt * 16 + (lane & 7) + ((lane >> 4) << 3);
        bC[nt] = (uint32_t)(r * 128) | (uint32_t)((r & 7) << 4);
    }
    const uint32_t bcx = (uint32_t)(((lane >> 3) & 1) << 4);

    float acc[4][4][4];
#pragma unroll
    for (int i = 0; i < 4; i++)
#pragma unroll
        for (int j = 0; j < 4; j++)
#pragma unroll
            for (int k = 0; k < 4; k++) acc[i][j][k] = 0.0f;

    const int total = 32;   // 2 pairs x 16 K-chunks of 64

    load_chunk(sb + 0 * STAGE_BYTES * 2, sb + 0 * STAGE_BYTES * 2 + STAGE_BYTES,
               aSrc[0], bSrc[0], ldbv, m0, bn, 0, tid);
    load_chunk(sb + 1 * STAGE_BYTES * 2, sb + 1 * STAGE_BYTES * 2 + STAGE_BYTES,
               aSrc[0], bSrc[0], ldbv, m0, bn, 64, tid);

    for (int ch = 0; ch < total; ch++) {
        if (ch == total - 1) asm volatile("cp.async.wait_group 0;" ::: "memory");
        else                 asm volatile("cp.async.wait_group 1;" ::: "memory");
        __syncthreads();

        int nc = ch + 2;
        if (nc < total) {
            int p = nc >> 4;
            int st = nc % 3;
            load_chunk(sb + st * STAGE_BYTES * 2, sb + st * STAGE_BYTES * 2 + STAGE_BYTES,
                       aSrc[p], bSrc[p], ldbv, m0, bn, (nc & 15) * 64, tid);
        }

        const uint32_t sA = sb + (ch % 3) * STAGE_BYTES * 2;
        const uint32_t sB = sA + STAGE_BYTES;

        uint32_t Af[2][4][4], Bf[2][2][4];
#pragma unroll
        for (int mt = 0; mt < 4; mt++) ldsm4(Af[0][mt], sA + (aC[mt] ^ acx));
#pragma unroll
        for (int nt = 0; nt < 2; nt++) ldsm4(Bf[0][nt], sB + (bC[nt] ^ bcx));
#pragma unroll
        for (int ks = 0; ks < 4; ks++) {
            const int cur = ks & 1, nxt = cur ^ 1;
            if (ks < 3) {
                const uint32_t qa = ((uint32_t)(ks + 1) << 5) | acx;
                const uint32_t qb = ((uint32_t)(ks + 1) << 5) | bcx;
#pragma unroll
                for (int mt = 0; mt < 4; mt++) ldsm4(Af[nxt][mt], sA + (aC[mt] ^ qa));
#pragma unroll
                for (int nt = 0; nt < 2; nt++) ldsm4(Bf[nxt][nt], sB + (bC[nt] ^ qb));
            }
#pragma unroll
            for (int mt = 0; mt < 4; mt++)
#pragma unroll
                for (int j = 0; j < 4; j++)
                    mma_f16(acc[mt][j], Af[cur][mt],
                            Bf[cur][j >> 1][(j & 1) * 2], Bf[cur][j >> 1][(j & 1) * 2 + 1]);
        }
    }

    // ---------------- fused epilogue ----------------
#pragma unroll
    for (int mt = 0; mt < 4; mt++) {
#pragma unroll
        for (int j = 0; j < 4; j++) {
            const int c0 = bn + wn * 32 + j * 8 + (lane & 3) * 2;
#pragma unroll
            for (int half = 0; half < 2; half++) {
                const int row = m0 + wm * 64 + mt * 16 + (lane >> 2) + half * 8;
                const size_t idx = (size_t)row * HID + c0;
                float v0 = acc[mt][j][half * 2 + 0];
                float v1 = acc[mt][j][half * 2 + 1];
                if (FINAL) {
                    float t0 = fast_tanh(v0 + bias[c0]);
                    float t1 = fast_tanh(v1 + bias[c0 + 1]);
                    float2 zz = __half22float2(*(const __half2*)(g_z16 + idx));
                    float2 hh = __half22float2(*(const __half2*)(g_hat16 + idx));
                    float2 ec = __half22float2(*(const __half2*)(g_ec16 + idx));
                    float2 hp = __half22float2(*(const __half2*)(g_h16 + idx));
                    float inv = g_inv[row];
                    out[idx]     = (1.0f - zz.x) * t0 + zz.x * hp.x + hh.x * ec.x * inv;
                    out[idx + 1] = (1.0f - zz.y) * t1 + zz.y * hp.y + hh.y * ec.y * inv;
                } else if (o == 0) {
                    float s0 = fast_sigmoid(v0 + bias[c0]);
                    float s1 = fast_sigmoid(v1 + bias[c0 + 1]);
                    float2 hh = __half22float2(*(const __half2*)(g_h16 + idx));
                    *(__half2*)(g_rh16 + idx) = __floats2half2_rn(s0 * hh.x, s1 * hh.y);
                } else if (o == 1) {
                    *(__half2*)(g_z16 + idx) =
                        __floats2half2_rn(fast_sigmoid(v0 + bias[c0]), fast_sigmoid(v1 + bias[c0 + 1]));
                } else if (o == 2) {
                    *(__half2*)(g_ec16 + idx) =
                        __floats2half2_rn(__expf(v0 + bias[c0]), __expf(v1 + bias[c0 + 1]));
                } else {
                    *(__half2*)(g_hat16 + idx) =
                        __floats2half2_rn(fmaxf(v0 + bias[c0], 0.0f), fmaxf(v1 + bias[c0 + 1], 0.0f));
                }
            }
        }
    }
}

// ---------------- batched fp32 -> fp16 convert (one launch) ----------------
struct ConvJob {
    const float4* src[10];
    __half2* dst[10];
    int end4[10];
};

#define CONV_TOTAL4 6815744

__global__ __launch_bounds__(256)
void convall(ConvJob j)
{
    const int gid = blockIdx.x * 256 + threadIdx.x;
#pragma unroll
    for (int rep = 0; rep < 2; rep++) {
        int i = gid + rep * (CONV_TOTAL4 / 2);
        int s = 0;
#pragma unroll
        for (int t = 0; t < 9; t++) s += (i >= j.end4[t]) ? 1 : 0;
        int base = (s == 0) ? 0 : j.end4[s - 1];
        int k = i - base;
        float4 f = j.src[s][k];
        j.dst[s][2 * k]     = __floats2half2_rn(f.x, f.y);
        j.dst[s][2 * k + 1] = __floats2half2_rn(f.z, f.w);
    }
}

// ---------------- row sum of exp(c): one warp per row, coalesced ----------------
__global__ __launch_bounds__(256)
void rowsum_kernel()
{
    const int lane = threadIdx.x & 31;
    const int warp = threadIdx.x >> 5;
    const int row = blockIdx.x * 8 + warp;
    const __half2* c2 = (const __half2*)g_ec16 + (size_t)row * 512;

    float s = 0.0f;
#pragma unroll
    for (int i = 0; i < 16; i++) {
        float2 v = __half22float2(c2[lane + i * 32]);
        s += v.x + v.y;
    }
#pragma unroll
    for (int off = 16; off > 0; off >>= 1) s += __shfl_xor_sync(0xffffffffu, s, off);
    if (lane == 0) g_inv[row] = 1.0f / s;
}

extern "C" void kernel_launch(void* const* d_in, const int* in_sizes, int n_in,
                              void* d_out, int out_size)
{
    (void)in_sizes; (void)n_in; (void)out_size;
    const float* x    = (const float*)d_in[0];
    const float* h    = (const float*)d_in[1];
    const float* Wxr  = (const float*)d_in[2];
    const float* Whr  = (const float*)d_in[3];
    const float* br   = (const float*)d_in[4];
    const float* Wxz  = (const float*)d_in[5];
    const float* Whz  = (const float*)d_in[6];
    const float* bz   = (const float*)d_in[7];
    const float* Wxh  = (const float*)d_in[8];
    const float* Whh  = (const float*)d_in[9];
    const float* bh   = (const float*)d_in[10];
    const float* Wc   = (const float*)d_in[11];
    const float* bc   = (const float*)d_in[12];
    const float* What = (const float*)d_in[13];
    const float* bhat = (const float*)d_in[14];
    float* out = (float*)d_out;

    __half *w16, *x16, *h16;
    cudaGetSymbolAddress((void**)&w16, g_w16);
    cudaGetSymbolAddress((void**)&x16, g_x16);
    cudaGetSymbolAddress((void**)&h16, g_h16);

    cudaFuncSetAttribute(gemm_tc<0>, cudaFuncAttributeMaxDynamicSharedMemorySize, SMEM_TOTAL);
    cudaFuncSetAttribute(gemm_tc<1>, cudaFuncAttributeMaxDynamicSharedMemorySize, SMEM_TOTAL);

    ConvJob j;
    const float* srcs[10] = {x, h, Wxr, Whr, Wxz, Whz, Wxh, Whh, Wc, What};
    __half* dsts[10] = {x16, h16, w16 + OFF_WXR, w16 + OFF_WHR, w16 + OFF_WXZ,
                        w16 + OFF_WHZ, w16 + OFF_WXH, w16 + OFF_WHH,
                        w16 + OFF_WC, w16 + OFF_WHAT};
    const int cnt4[10] = {2097152, 2097152, 262144, 262144, 262144, 262144,
                          262144, 262144, 524288, 524288};
    int acc4 = 0;
    for (int i = 0; i < 10; i++) {
        j.src[i] = (const float4*)srcs[i];
        j.dst[i] = (__half2*)dsts[i];
        acc4 += cnt4[i];
        j.end4[i] = acc4;
    }

    convall<<<CONV_TOTAL4 / 2 / 256, 256>>>(j);

    // fused multi-output GEMM: r (->rh fp16), z16, exp(c)16, hat16
    gemm_tc<0><<<dim3(32, 64), THREADS, SMEM_TOTAL>>>(br, bz, bh, bc, bhat, nullptr);

    // g_inv[row] = 1 / rowsum(exp(c))
    rowsum_kernel<<<BATCH / 8, 256>>>();

    // final: acc = rh@Whh^T + x@Wxh^T ; out = (1-z)*tanh(acc+bh) + z*h + hat*ec*inv
    gemm_tc<1><<<dim3(8, 64), THREADS, SMEM_TOTAL>>>(br, bz, bh, bc, bhat, out);
}

// round 17
// speedup vs baseline: 1.0882x; 1.0039x over previous
#include <cuda_runtime.h>
#include <cuda_fp16.h>
#include <cstdint>
#include <math.h>

#define BATCH 8192
#define HID   1024
#define M1    1048576

// ---------------- device scratch (no allocations allowed) ----------------
__device__ __half g_w16[10 * M1];
__device__ __half g_x16[BATCH * HID];
__device__ __half g_h16[BATCH * HID];
__device__ __half g_rh16[BATCH * HID];
__device__ __half g_z16[BATCH * HID];
__device__ __half g_ec16[BATCH * HID];   // exp(c_pre + bc)
__device__ __half g_hat16[BATCH * HID];  // relu(hat_pre + bhat), unscaled
__device__ float  g_sum[BATCH];          // rowsum(exp(c)), via atomics

#define OFF_WXR  0
#define OFF_WHR  (1 * M1)
#define OFF_WXZ  (2 * M1)
#define OFF_WHZ  (3 * M1)
#define OFF_WXH  (4 * M1)
#define OFF_WHH  (5 * M1)
#define OFF_WC   (6 * M1)
#define OFF_WHAT (8 * M1)

// ---------------- helpers ----------------
__device__ __forceinline__ uint32_t smem_u32(const void* p) {
    uint32_t a;
    asm("{ .reg .u64 t; cvta.to.shared.u64 t, %1; cvt.u32.u64 %0, t; }" : "=r"(a) : "l"(p));
    return a;
}
__device__ __forceinline__ void cp16(uint32_t s, const void* g) {
    asm volatile("cp.async.cg.shared.global [%0], [%1], 16;" :: "r"(s), "l"(g));
}
__device__ __forceinline__ void ldsm4(uint32_t (&r)[4], uint32_t addr) {
    asm volatile("ldmatrix.sync.aligned.m8n8.x4.shared.b16 {%0,%1,%2,%3}, [%4];"
        : "=r"(r[0]), "=r"(r[1]), "=r"(r[2]), "=r"(r[3]) : "r"(addr));
}
__device__ __forceinline__ void mma_f16(float (&d)[4], const uint32_t (&a)[4],
                                        uint32_t b0, uint32_t b1) {
    asm volatile("mma.sync.aligned.m16n8k16.row.col.f32.f16.f16.f32 "
        "{%0,%1,%2,%3}, {%4,%5,%6,%7}, {%8,%9}, {%0,%1,%2,%3};"
        : "+f"(d[0]), "+f"(d[1]), "+f"(d[2]), "+f"(d[3])
        : "r"(a[0]), "r"(a[1]), "r"(a[2]), "r"(a[3]), "r"(b0), "r"(b1));
}
__device__ __forceinline__ float fast_tanh(float x) {
    float r;
    asm("tanh.approx.f32 %0, %1;" : "=f"(r) : "f"(x));
    return r;
}
__device__ __forceinline__ float fast_sigmoid(float x) {
    return fmaf(fast_tanh(0.5f * x), 0.5f, 0.5f);
}

// ---------------- GEMM config (BM=128, 2 CTA/SM, MT=4) ----------------
#define THREADS 256
#define STAGE_BYTES 16384
#define SMEM_TOTAL (3 * 2 * STAGE_BYTES)

__device__ __forceinline__ void load_chunk(uint32_t sA, uint32_t sB,
    const __half* __restrict__ a, const __half* __restrict__ b,
    int ldb, int m0, int bn, int k0, int tid)
{
#pragma unroll
    for (int it = 0; it < 4; it++) {
        int s = tid + it * 256;
        int r = s >> 3, cc = s & 7;
        uint32_t off = r * 128 + ((cc * 16) ^ ((r & 7) << 4));
        cp16(sA + off, a + (size_t)(m0 + r) * 1024 + k0 + cc * 8);
    }
#pragma unroll
    for (int it = 0; it < 4; it++) {
        int s = tid + it * 256;
        int r = s >> 3, cc = s & 7;
        uint32_t off = r * 128 + ((cc * 16) ^ ((r & 7) << 4));
        cp16(sB + off, b + (size_t)(bn + r) * (size_t)ldb + k0 + cc * 8);
    }
    asm volatile("cp.async.commit_group;" ::: "memory");
}

// FINAL=0: o=0..3 (r,z,expc,hat), grid (32, 64): o=bx>>3, bn=(bx&7)*128 — all 32-chunk
// FINAL=1: pairs {rh@Whh^T, x@Wxh^T} accumulated -> fused output, grid (8, 64)
template <int FINAL>
__global__ __launch_bounds__(THREADS, 2)
void gemm_tc(const float* __restrict__ br, const float* __restrict__ bz,
             const float* __restrict__ bh, const float* __restrict__ bc,
             const float* __restrict__ bhat, float* __restrict__ out)
{
    extern __shared__ char smem[];
    const uint32_t sb = smem_u32(smem);
    const int tid = threadIdx.x;
    const int lane = tid & 31;
    const int wid = tid >> 5;
    const int wm = wid >> 2;
    const int wn = wid & 3;
    const int m0 = blockIdx.y * 128;

    int o, bn;
    if (FINAL) { o = 4; bn = blockIdx.x * 128; }
    else       { o = blockIdx.x >> 3; bn = (blockIdx.x & 7) * 128; }

    const __half *aSrc[2] = {g_x16, g_h16};
    const __half *bSrc[2] = {0, 0};
    int ldbv = 1024;
    const float* bias = 0;
    switch (o) {
        case 0: bSrc[0] = g_w16 + OFF_WXR; bSrc[1] = g_w16 + OFF_WHR; bias = br; break;
        case 1: bSrc[0] = g_w16 + OFF_WXZ; bSrc[1] = g_w16 + OFF_WHZ; bias = bz; break;
        case 2: bSrc[0] = g_w16 + OFF_WC;  bSrc[1] = g_w16 + OFF_WC + 1024;
                ldbv = 2048; bias = bc; break;
        case 3: bSrc[0] = g_w16 + OFF_WHAT; bSrc[1] = g_w16 + OFF_WHAT + 1024;
                ldbv = 2048; bias = bhat; break;
        default: aSrc[0] = g_rh16; aSrc[1] = g_x16;
                 bSrc[0] = g_w16 + OFF_WHH; bSrc[1] = g_w16 + OFF_WXH;
                 bias = bh; break;
    }

    uint32_t aC[4];
#pragma unroll
    for (int mt = 0; mt < 4; mt++) {
        int r = wm * 64 + mt * 16 + (lane & 15);
        aC[mt] = (uint32_t)(r * 128) | (uint32_t)((r & 7) << 4);
    }
    const uint32_t acx = (uint32_t)((lane >> 4) << 4);
    uint32_t bC[2];
#pragma unroll
    for (int nt = 0; nt < 2; nt++) {
        int r = wn * 32 + nt * 16 + (lane & 7) + ((lane >> 4) << 3);
        bC[nt] = (uint32_t)(r * 128) | (uint32_t)((r & 7) << 4);
    }
    const uint32_t bcx = (uint32_t)(((lane >> 3) & 1) << 4);

    float acc[4][4][4];
#pragma unroll
    for (int i = 0; i < 4; i++)
#pragma unroll
        for (int j = 0; j < 4; j++)
#pragma unroll
            for (int k = 0; k < 4; k++) acc[i][j][k] = 0.0f;

    const int total = 32;   // 2 pairs x 16 K-chunks of 64

    load_chunk(sb + 0 * STAGE_BYTES * 2, sb + 0 * STAGE_BYTES * 2 + STAGE_BYTES,
               aSrc[0], bSrc[0], ldbv, m0, bn, 0, tid);
    load_chunk(sb + 1 * STAGE_BYTES * 2, sb + 1 * STAGE_BYTES * 2 + STAGE_BYTES,
               aSrc[0], bSrc[0], ldbv, m0, bn, 64, tid);

    for (int ch = 0; ch < total; ch++) {
        if (ch == total - 1) asm volatile("cp.async.wait_group 0;" ::: "memory");
        else                 asm volatile("cp.async.wait_group 1;" ::: "memory");
        __syncthreads();

        int nc = ch + 2;
        if (nc < total) {
            int p = nc >> 4;
            int st = nc % 3;
            load_chunk(sb + st * STAGE_BYTES * 2, sb + st * STAGE_BYTES * 2 + STAGE_BYTES,
                       aSrc[p], bSrc[p], ldbv, m0, bn, (nc & 15) * 64, tid);
        }

        const uint32_t sA = sb + (ch % 3) * STAGE_BYTES * 2;
        const uint32_t sB = sA + STAGE_BYTES;

        uint32_t Af[2][4][4], Bf[2][2][4];
#pragma unroll
        for (int mt = 0; mt < 4; mt++) ldsm4(Af[0][mt], sA + (aC[mt] ^ acx));
#pragma unroll
        for (int nt = 0; nt < 2; nt++) ldsm4(Bf[0][nt], sB + (bC[nt] ^ bcx));
#pragma unroll
        for (int ks = 0; ks < 4; ks++) {
            const int cur = ks & 1, nxt = cur ^ 1;
            if (ks < 3) {
                const uint32_t qa = ((uint32_t)(ks + 1) << 5) | acx;
                const uint32_t qb = ((uint32_t)(ks + 1) << 5) | bcx;
#pragma unroll
                for (int mt = 0; mt < 4; mt++) ldsm4(Af[nxt][mt], sA + (aC[mt] ^ qa));
#pragma unroll
                for (int nt = 0; nt < 2; nt++) ldsm4(Bf[nxt][nt], sB + (bC[nt] ^ qb));
            }
#pragma unroll
            for (int mt = 0; mt < 4; mt++)
#pragma unroll
                for (int j = 0; j < 4; j++)
                    mma_f16(acc[mt][j], Af[cur][mt],
                            Bf[cur][j >> 1][(j & 1) * 2], Bf[cur][j >> 1][(j & 1) * 2 + 1]);
        }
    }

    // ---------------- fused epilogue ----------------
    float rs[4][2];   // per-(mt,half) partial row sums of exp(c) (o==2 only)
#pragma unroll
    for (int i = 0; i < 4; i++) { rs[i][0] = 0.0f; rs[i][1] = 0.0f; }

#pragma unroll
    for (int mt = 0; mt < 4; mt++) {
#pragma unroll
        for (int j = 0; j < 4; j++) {
            const int c0 = bn + wn * 32 + j * 8 + (lane & 3) * 2;
#pragma unroll
            for (int half = 0; half < 2; half++) {
                const int row = m0 + wm * 64 + mt * 16 + (lane >> 2) + half * 8;
                const size_t idx = (size_t)row * HID + c0;
                float v0 = acc[mt][j][half * 2 + 0];
                float v1 = acc[mt][j][half * 2 + 1];
                if (FINAL) {
                    float t0 = fast_tanh(v0 + bias[c0]);
                    float t1 = fast_tanh(v1 + bias[c0 + 1]);
                    float2 zz = __half22float2(*(const __half2*)(g_z16 + idx));
                    float2 hh = __half22float2(*(const __half2*)(g_hat16 + idx));
                    float2 ec = __half22float2(*(const __half2*)(g_ec16 + idx));
                    float2 hp = __half22float2(*(const __half2*)(g_h16 + idx));
                    float inv = __fdividef(1.0f, g_sum[row]);
                    out[idx]     = (1.0f - zz.x) * t0 + zz.x * hp.x + hh.x * ec.x * inv;
                    out[idx + 1] = (1.0f - zz.y) * t1 + zz.y * hp.y + hh.y * ec.y * inv;
                } else if (o == 0) {
                    float s0 = fast_sigmoid(v0 + bias[c0]);
                    float s1 = fast_sigmoid(v1 + bias[c0 + 1]);
                    float2 hh = __half22float2(*(const __half2*)(g_h16 + idx));
                    *(__half2*)(g_rh16 + idx) = __floats2half2_rn(s0 * hh.x, s1 * hh.y);
                } else if (o == 1) {
                    *(__half2*)(g_z16 + idx) =
                        __floats2half2_rn(fast_sigmoid(v0 + bias[c0]), fast_sigmoid(v1 + bias[c0 + 1]));
                } else if (o == 2) {
                    float e0 = __expf(v0 + bias[c0]);
                    float e1 = __expf(v1 + bias[c0 + 1]);
                    rs[mt][half] += e0 + e1;
                    *(__half2*)(g_ec16 + idx) = __floats2half2_rn(e0, e1);
                } else {
                    *(__half2*)(g_hat16 + idx) =
                        __floats2half2_rn(fmaxf(v0 + bias[c0], 0.0f), fmaxf(v1 + bias[c0 + 1], 0.0f));
                }
            }
        }
    }

    if (!FINAL && o == 2) {
        // reduce the 4 lanes (lane&3) sharing each row, then one atomic per row-slice
#pragma unroll
        for (int mt = 0; mt < 4; mt++) {
#pragma unroll
            for (int half = 0; half < 2; half++) {
                float s = rs[mt][half];
                s += __shfl_xor_sync(0xffffffffu, s, 1);
                s += __shfl_xor_sync(0xffffffffu, s, 2);
                if ((lane & 3) == 0) {
                    const int row = m0 + wm * 64 + mt * 16 + (lane >> 2) + half * 8;
                    atomicAdd(&g_sum[row], s);
                }
            }
        }
    }
}

// ---------------- batched fp32 -> fp16 convert (one launch) + zero g_sum ----------------
struct ConvJob {
    const float4* src[10];
    __half2* dst[10];
    int end4[10];
};

#define CONV_TOTAL4 6815744

__global__ __launch_bounds__(256)
void convall(ConvJob j)
{
    const int gid = blockIdx.x * 256 + threadIdx.x;
    if (gid < BATCH) g_sum[gid] = 0.0f;
#pragma unroll
    for (int rep = 0; rep < 2; rep++) {
        int i = gid + rep * (CONV_TOTAL4 / 2);
        int s = 0;
#pragma unroll
        for (int t = 0; t < 9; t++) s += (i >= j.end4[t]) ? 1 : 0;
        int base = (s == 0) ? 0 : j.end4[s - 1];
        int k = i - base;
        float4 f = j.src[s][k];
        j.dst[s][2 * k]     = __floats2half2_rn(f.x, f.y);
        j.dst[s][2 * k + 1] = __floats2half2_rn(f.z, f.w);
    }
}

extern "C" void kernel_launch(void* const* d_in, const int* in_sizes, int n_in,
                              void* d_out, int out_size)
{
    (void)in_sizes; (void)n_in; (void)out_size;
    const float* x    = (const float*)d_in[0];
    const float* h    = (const float*)d_in[1];
    const float* Wxr  = (const float*)d_in[2];
    const float* Whr  = (const float*)d_in[3];
    const float* br   = (const float*)d_in[4];
    const float* Wxz  = (const float*)d_in[5];
    const float* Whz  = (const float*)d_in[6];
    const float* bz   = (const float*)d_in[7];
    const float* Wxh  = (const float*)d_in[8];
    const float* Whh  = (const float*)d_in[9];
    const float* bh   = (const float*)d_in[10];
    const float* Wc   = (const float*)d_in[11];
    const float* bc   = (const float*)d_in[12];
    const float* What = (const float*)d_in[13];
    const float* bhat = (const float*)d_in[14];
    float* out = (float*)d_out;

    __half *w16, *x16, *h16;
    cudaGetSymbolAddress((void**)&w16, g_w16);
    cudaGetSymbolAddress((void**)&x16, g_x16);
    cudaGetSymbolAddress((void**)&h16, g_h16);

    cudaFuncSetAttribute(gemm_tc<0>, cudaFuncAttributeMaxDynamicSharedMemorySize, SMEM_TOTAL);
    cudaFuncSetAttribute(gemm_tc<1>, cudaFuncAttributeMaxDynamicSharedMemorySize, SMEM_TOTAL);

    ConvJob j;
    const float* srcs[10] = {x, h, Wxr, Whr, Wxz, Whz, Wxh, Whh, Wc, What};
    __half* dsts[10] = {x16, h16, w16 + OFF_WXR, w16 + OFF_WHR, w16 + OFF_WXZ,
                        w16 + OFF_WHZ, w16 + OFF_WXH, w16 + OFF_WHH,
                        w16 + OFF_WC, w16 + OFF_WHAT};
    const int cnt4[10] = {2097152, 2097152, 262144, 262144, 262144, 262144,
                          262144, 262144, 524288, 524288};
    int acc4 = 0;
    for (int i = 0; i < 10; i++) {
        j.src[i] = (const float4*)srcs[i];
        j.dst[i] = (__half2*)dsts[i];
        acc4 += cnt4[i];
        j.end4[i] = acc4;
    }

    convall<<<CONV_TOTAL4 / 2 / 256, 256>>>(j);

    // fused multi-output GEMM: r (->rh fp16), z16, exp(c)16 (+row sums), hat16
    gemm_tc<0><<<dim3(32, 64), THREADS, SMEM_TOTAL>>>(br, bz, bh, bc, bhat, nullptr);

    // final: acc = rh@Whh^T + x@Wxh^T ; out = (1-z)*tanh(acc+bh) + z*h + hat*ec/g_sum
    gemm_tc<1><<<dim3(8, 64), THREADS, SMEM_TOTAL>>>(br, bz, bh, bc, bhat, out);
}